// round 15
// baseline (speedup 1.0000x reference)
#include <cuda_runtime.h>

// DNAShapeNet fused kernel, R12: R4 (705us) with conv weights for layers 2-4
// moved to __constant__ memory. Goal: warp-uniform LDCU weight loads let
// ptxas place the FFMA2 weight operand in uniform registers, cutting the
// per-instruction vector-RF bank reads from 3 to 2 (rt 3 -> 2, +50% FMA2
// throughput). All other structure identical to R4.

#define BATCH    128
#define SEQ      8192
#define TSIZE    512
#define NTHREADS 512
#define WPAD     592
#define HALO     7

typedef unsigned long long ull;

// constant weights: raw [cout][cin][K] layouts, w1 then w2 then w3
#define CW_OFF1 0
#define CW_OFF2 3072
#define CW_OFF3 8192
__constant__ float cW[15360];

// ---- smem layout (float offsets) ----
#define OFF_BUFA 0
#define OFF_BUFB (OFF_BUFA + 32*WPAD)
#define OFF_W0   (OFF_BUFB + 32*WPAD)    // interleaved pairs, 384 floats
#define OFF_SC   (OFF_W0 + 384)
#define OFF_SH   (OFF_SC + 128)
#define OFF_BI   (OFF_SH + 128)
#define OFF_FW1  (OFF_BI + 128)
#define OFF_FB1  (OFF_FW1 + 512)
#define OFF_FW2  (OFF_FB1 + 16)
#define OFF_FB2  (OFF_FW2 + 16)
#define SMEM_FLOATS (OFF_FB2 + 1)
#define SMEM_BYTES  (SMEM_FLOATS * 4)

struct Ptrs {
    const float* x;
    const float* w[4];
    const float* b[4];
    const float* g[4];
    const float* bb[4];
    const float* rm[4];
    const float* rv[4];
    const float* fw1;
    const float* fb1;
    const float* fw2;
    const float* fb2;
};

__device__ __forceinline__ ull pack2(float lo, float hi) {
    ull r;
    asm("mov.b64 %0, {%1, %2};" : "=l"(r) : "f"(lo), "f"(hi));
    return r;
}
__device__ __forceinline__ void unpack2(ull v, float& lo, float& hi) {
    asm("mov.b64 {%0, %1}, %2;" : "=f"(lo), "=f"(hi) : "l"(v));
}
__device__ __forceinline__ ull fma2(ull a, ull b, ull c) {
    ull d;
    asm("fma.rn.f32x2 %0, %1, %2, %3;" : "=l"(d) : "l"(a), "l"(b), "l"(c));
    return d;
}
// plain C++ pack (no inline asm) — keeps the value eligible for ptxas
// uniform-register promotion when both halves are warp-uniform.
__device__ __forceinline__ ull packc(float lo, float hi) {
    float2 v = make_float2(lo, hi);
    ull r;
    __builtin_memcpy(&r, &v, 8);
    return r;
}

// CH output positions for one input channel, channel-pair packed.
template<int K, int SOFF, int CH>
__device__ __forceinline__ void conv_chunk_cp(const float* __restrict__ xin,
                                              const ull* __restrict__ wp,
                                              ull* __restrict__ acc)
{
    constexpr int NS = SOFF + CH + K - 1;   // scalars spanned from even base
    constexpr int NP = (NS + 1) >> 1;       // float2 loads

    float s[2 * NP];
#pragma unroll
    for (int i = 0; i < NP; ++i) {
        float2 v = ((const float2*)xin)[i];
        s[2 * i] = v.x; s[2 * i + 1] = v.y;
    }

    ull bb[NS];                             // broadcast pairs {s,s}
#pragma unroll
    for (int u = SOFF; u < NS; ++u) bb[u] = pack2(s[u], s[u]);

#pragma unroll
    for (int t = 0; t < K; ++t)
#pragma unroll
        for (int p = 0; p < CH; ++p)
            acc[p] = fma2(bb[SOFF + p + t], wp[t], acc[p]);
}

// BN/ReLU epilogue + store.
template <int WOUT, int LOFF>
__device__ __forceinline__ void store_outputs(
    float* __restrict__ sout, const ull* __restrict__ acc,
    const float* __restrict__ sc, const float* __restrict__ sh,
    const float* __restrict__ bi, int cp, int j, int seq_base)
{
    const int co0 = 2 * cp;
    const float sc0 = sc[co0], sh0 = sh[co0], bi0 = bi[co0];
    const float sc1 = sc[co0 + 1], sh1 = sh[co0 + 1], bi1 = bi[co0 + 1];
    float* o0 = sout + co0 * WPAD;
    float* o1 = o0 + WPAD;

#pragma unroll
    for (int i = 0; i < 18; ++i) {
        int pl = j * 18 + i;
        if (pl < WOUT) {
            int u = LOFF + pl;
            int seq = seq_base + u;
            bool inb = (seq >= 0 && seq < SEQ);
            float a0, a1;
            unpack2(acc[i], a0, a1);
            float y0 = fmaxf(a0 + bi0, 0.f);
            float y1 = fmaxf(a1 + bi1, 0.f);
            o0[u] = inb ? fmaf(y0, sc0, sh0) : 0.f;
            o1[u] = inb ? fmaf(y1, sc1, sh1) : 0.f;
        }
    }
}

// Layer 1 (CIN=4): weights from smem (interleaved pairs), as in R4.
template <int K, int WOUT, int LOFF>
__device__ __forceinline__ void conv_layer_l1(
    const float* __restrict__ sin, float* __restrict__ sout,
    const float* __restrict__ wint,
    const float* __restrict__ sc, const float* __restrict__ sh,
    const float* __restrict__ bi,
    int cp, int j, int seq_base)
{
    constexpr int H = K / 2;
    constexpr int DELTA = (LOFF - H) & 1;

    ull acc[18];
    const ull z = pack2(0.f, 0.f);
#pragma unroll
    for (int p = 0; p < 18; ++p) acc[p] = z;

    const int abase = (LOFF - H - DELTA) + j * 18;

#pragma unroll 4
    for (int cin = 0; cin < 4; ++cin) {
        const ull* wsm = (const ull*)(wint + (cp * 4 + cin) * (2 * K));
        ull wp[K];
#pragma unroll
        for (int t = 0; t < K; ++t) wp[t] = wsm[t];
        conv_chunk_cp<K, DELTA, 18>(sin + cin * WPAD + abase, wp, acc);
    }
    store_outputs<WOUT, LOFF>(sout, acc, sc, sh, bi, cp, j, seq_base);
}

// Layers 2-4 (CIN=32): weights from __constant__ (warp-uniform LDCU path).
// Two scalar const loads per tap, packed in plain C++ -> ptxas may keep the
// weight operand in uniform registers.
template <int K, int WOUT, int LOFF, int CWOFF>
__device__ __forceinline__ void conv_layer_cw(
    const float* __restrict__ sin, float* __restrict__ sout,
    const float* __restrict__ sc, const float* __restrict__ sh,
    const float* __restrict__ bi,
    int cp, int j, int seq_base)
{
    constexpr int H = K / 2;
    constexpr int DELTA = (LOFF - H) & 1;

    ull acc[18];
    const ull z = pack2(0.f, 0.f);
#pragma unroll
    for (int p = 0; p < 18; ++p) acc[p] = z;

    const int abase = (LOFF - H - DELTA) + j * 18;
    const float* w0base = cW + CWOFF + (2 * cp) * (32 * K);   // channel 2cp
    const float* w1base = w0base + 32 * K;                    // channel 2cp+1

#pragma unroll 1
    for (int cin = 0; cin < 32; ++cin) {
        ull wp[K];
#pragma unroll
        for (int t = 0; t < K; ++t)
            wp[t] = packc(w0base[cin * K + t], w1base[cin * K + t]);

        conv_chunk_cp<K, DELTA, 18>(sin + cin * WPAD + abase, wp, acc);
    }
    store_outputs<WOUT, LOFF>(sout, acc, sc, sh, bi, cp, j, seq_base);
}

__global__ void __launch_bounds__(NTHREADS, 1)
dna_fused_kernel(Ptrs P, float* __restrict__ out)
{
    extern __shared__ float sm[];
    const int tid = threadIdx.x;
    const int ts  = blockIdx.x * TSIZE;
    const int b   = blockIdx.y;
    const int seq_base = ts - HALO;

    float* bufA = sm + OFF_BUFA;
    float* bufB = sm + OFF_BUFB;
    float* sW0 = sm + OFF_W0;
    float* sSC = sm + OFF_SC;
    float* sSH = sm + OFF_SH;
    float* sBI = sm + OFF_BI;
    float* sFW1 = sm + OFF_FW1;
    float* sFB1 = sm + OFF_FB1;
    float* sFW2 = sm + OFF_FW2;
    float* sFB2 = sm + OFF_FB2;

    // phase 1: halo-only zero fill of both activation buffers.
    {
        constexpr int ZPR = 8 + (WPAD - 512);   // 88 zeros per row
        for (int idx = tid; idx < 64 * ZPR; idx += NTHREADS) {
            int r = idx / ZPR, c = idx - r * ZPR;
            int u = (c < 8) ? c : (504 + c);
            sm[r * WPAD + u] = 0.f;
        }
    }

    // layer-1 weights: interleaved pairs in smem
    {
        const int n = 4 * 3;
        for (int i = tid; i < 16 * n; i += NTHREADS) {
            int cp = i / n, r = i - cp * n;
            sW0[2 * i]     = P.w[0][(2 * cp)     * n + r];
            sW0[2 * i + 1] = P.w[0][(2 * cp + 1) * n + r];
        }
    }

    for (int i = tid; i < 16 * 32; i += NTHREADS) sFW1[i] = P.fw1[i];
    if (tid < 16) { sFB1[tid] = P.fb1[tid]; sFW2[tid] = P.fw2[tid]; }
    if (tid == 0) sFB2[0] = P.fb2[0];

    if (tid < 128) {
        int l = tid >> 5, c = tid & 31;
        float inv = P.g[l][c] * rsqrtf(P.rv[l][c] + 1e-5f);
        sSC[tid] = inv;
        sSH[tid] = P.bb[l][c] - P.rm[l][c] * inv;
        sBI[tid] = P.b[l][c];
    }
    __syncthreads();

    // phase 2: input tile (4 channels, width 526) over the zeroed halo
    constexpr int WIN = TSIZE + 2 * HALO;   // 526
    for (int idx = tid; idx < 4 * WIN; idx += NTHREADS) {
        int cin = idx / WIN;
        int u = idx - cin * WIN;
        int seq = seq_base + u;
        if (seq >= 0 && seq < SEQ)
            bufA[cin * WPAD + u] = P.x[(b * 4 + cin) * SEQ + seq];
    }
    __syncthreads();

    const int cp = tid >> 5;    // warp -> channel pair [0,16)
    const int j  = tid & 31;    // lane -> 18-pos slice [0,32)

    conv_layer_l1<3, 524, 1>(bufA, bufB, sW0, sSC, sSH, sBI, cp, j, seq_base);
    __syncthreads();
    conv_layer_cw<3, 522, 2, CW_OFF1>(bufB, bufA, sSC + 32, sSH + 32, sBI + 32, cp, j, seq_base);
    __syncthreads();
    conv_layer_cw<5, 518, 4, CW_OFF2>(bufA, bufB, sSC + 64, sSH + 64, sBI + 64, cp, j, seq_base);
    __syncthreads();
    conv_layer_cw<7, 512, 7, CW_OFF3>(bufB, bufA, sSC + 96, sSH + 96, sBI + 96, cp, j, seq_base);
    __syncthreads();

    // ---- per-position MLP: 32 -> 16 (ReLU) -> 1 ; one thread per position ----
    float yc[32];
#pragma unroll
    for (int c = 0; c < 32; ++c) yc[c] = bufA[c * WPAD + HALO + tid];

    float o = sFB2[0];
#pragma unroll
    for (int i = 0; i < 16; ++i) {
        float h = sFB1[i];
#pragma unroll
        for (int c = 0; c < 32; ++c) h = fmaf(sFW1[i * 32 + c], yc[c], h);
        o = fmaf(fmaxf(h, 0.f), sFW2[i], o);
    }
    out[b * SEQ + ts + tid] = o;
}

extern "C" void kernel_launch(void* const* d_in, const int* in_sizes, int n_in,
                              void* d_out, int out_size)
{
    Ptrs P;
    P.x = (const float*)d_in[0];
    for (int l = 0; l < 4; ++l) {
        P.w[l]  = (const float*)d_in[1 + 6 * l];
        P.b[l]  = (const float*)d_in[2 + 6 * l];
        P.g[l]  = (const float*)d_in[3 + 6 * l];
        P.bb[l] = (const float*)d_in[4 + 6 * l];
        P.rm[l] = (const float*)d_in[5 + 6 * l];
        P.rv[l] = (const float*)d_in[6 + 6 * l];
    }
    P.fw1 = (const float*)d_in[25];
    P.fb1 = (const float*)d_in[26];
    P.fw2 = (const float*)d_in[27];
    P.fb2 = (const float*)d_in[28];

    // raw-layout conv weights for layers 2-4 into constant memory
    // (device-to-device async memcpy: graph-capturable, no allocation)
    cudaMemcpyToSymbolAsync(cW, d_in[7],  3072 * 4, CW_OFF1 * 4,
                            cudaMemcpyDeviceToDevice, 0);
    cudaMemcpyToSymbolAsync(cW, d_in[13], 5120 * 4, CW_OFF2 * 4,
                            cudaMemcpyDeviceToDevice, 0);
    cudaMemcpyToSymbolAsync(cW, d_in[19], 7168 * 4, CW_OFF3 * 4,
                            cudaMemcpyDeviceToDevice, 0);

    cudaFuncSetAttribute(dna_fused_kernel,
                         cudaFuncAttributeMaxDynamicSharedMemorySize, SMEM_BYTES);

    dim3 grid(SEQ / TSIZE, BATCH);
    dna_fused_kernel<<<grid, NTHREADS, SMEM_BYTES>>>(P, (float*)d_out);
}

// round 16
// speedup vs baseline: 1.0501x; 1.0501x over previous
#include <cuda_runtime.h>

// DNAShapeNet fused kernel, R13: R4 (705us) with layer-4 chunk reduced from
// 18 to 16 positions — 32 lanes x 16 = 512 = exact L4 output width, removing
// the 12.5% masked-out FMA2 waste in the largest layer. All else as R4.

#define BATCH    128
#define SEQ      8192
#define TSIZE    512
#define NTHREADS 512
#define WPAD     592
#define HALO     7

typedef unsigned long long ull;

// ---- smem layout (float offsets) ----
#define OFF_BUFA 0
#define OFF_BUFB (OFF_BUFA + 32*WPAD)
#define OFF_W0   (OFF_BUFB + 32*WPAD)
#define OFF_W1   (OFF_W0 + 384)
#define OFF_W2   (OFF_W1 + 3072)
#define OFF_W3   (OFF_W2 + 5120)
#define OFF_SC   (OFF_W3 + 7168)
#define OFF_SH   (OFF_SC + 128)
#define OFF_BI   (OFF_SH + 128)
#define OFF_FW1  (OFF_BI + 128)
#define OFF_FB1  (OFF_FW1 + 512)
#define OFF_FW2  (OFF_FB1 + 16)
#define OFF_FB2  (OFF_FW2 + 16)
#define SMEM_FLOATS (OFF_FB2 + 1)
#define SMEM_BYTES  (SMEM_FLOATS * 4)

struct Ptrs {
    const float* x;
    const float* w[4];
    const float* b[4];
    const float* g[4];
    const float* bb[4];
    const float* rm[4];
    const float* rv[4];
    const float* fw1;
    const float* fb1;
    const float* fw2;
    const float* fb2;
};

__device__ __forceinline__ ull pack2(float lo, float hi) {
    ull r;
    asm("mov.b64 %0, {%1, %2};" : "=l"(r) : "f"(lo), "f"(hi));
    return r;
}
__device__ __forceinline__ void unpack2(ull v, float& lo, float& hi) {
    asm("mov.b64 {%0, %1}, %2;" : "=f"(lo), "=f"(hi) : "l"(v));
}
__device__ __forceinline__ ull fma2(ull a, ull b, ull c) {
    ull d;
    asm("fma.rn.f32x2 %0, %1, %2, %3;" : "=l"(d) : "l"(a), "l"(b), "l"(c));
    return d;
}

// CH output positions for one input channel, channel-pair packed.
template<int K, int SOFF, int CH>
__device__ __forceinline__ void conv_chunk_cp(const float* __restrict__ xin,
                                              const ull* __restrict__ wp,
                                              ull* __restrict__ acc)
{
    constexpr int NS = SOFF + CH + K - 1;   // scalars spanned from even base
    constexpr int NP = (NS + 1) >> 1;       // float2 loads

    float s[2 * NP];
#pragma unroll
    for (int i = 0; i < NP; ++i) {
        float2 v = ((const float2*)xin)[i];
        s[2 * i] = v.x; s[2 * i + 1] = v.y;
    }

    ull bb[NS];                             // broadcast pairs {s,s}
#pragma unroll
    for (int u = SOFF; u < NS; ++u) bb[u] = pack2(s[u], s[u]);

#pragma unroll
    for (int t = 0; t < K; ++t)
#pragma unroll
        for (int p = 0; p < CH; ++p)
            acc[p] = fma2(bb[SOFF + p + t], wp[t], acc[p]);
}

// One conv+ReLU+BN layer, smem -> smem. Thread (cp, j) computes channels
// {2cp, 2cp+1} at CH positions starting at LOFF + j*CH.
template <int CIN, int K, int WOUT, int LOFF, int CH, int UNROLL>
__device__ __forceinline__ void conv_layer_cp(
    const float* __restrict__ sin, float* __restrict__ sout,
    const float* __restrict__ wint,
    const float* __restrict__ sc, const float* __restrict__ sh,
    const float* __restrict__ bi,
    int cp, int j, int seq_base)
{
    constexpr int H = K / 2;
    constexpr int DELTA = (LOFF - H) & 1;        // parity fix -> even base
    constexpr bool FULL = (32 * CH == WOUT);     // exact coverage -> no mask

    ull acc[CH];
    const ull z = pack2(0.f, 0.f);
#pragma unroll
    for (int p = 0; p < CH; ++p) acc[p] = z;

    const int abase = (LOFF - H - DELTA) + j * CH;   // even

#pragma unroll UNROLL
    for (int cin = 0; cin < CIN; ++cin) {
        const ull* wsm = (const ull*)(wint + (cp * CIN + cin) * (2 * K));
        ull wp[K];
#pragma unroll
        for (int t = 0; t < K; ++t) wp[t] = wsm[t];   // LDS.64, warp-uniform

        conv_chunk_cp<K, DELTA, CH>(sin + cin * WPAD + abase, wp, acc);
    }

    const int co0 = 2 * cp;
    const float sc0 = sc[co0], sh0 = sh[co0], bi0 = bi[co0];
    const float sc1 = sc[co0 + 1], sh1 = sh[co0 + 1], bi1 = bi[co0 + 1];
    float* o0 = sout + co0 * WPAD;
    float* o1 = o0 + WPAD;

#pragma unroll
    for (int i = 0; i < CH; ++i) {
        int pl = j * CH + i;
        if (FULL || pl < WOUT) {
            int u = LOFF + pl;
            int seq = seq_base + u;
            bool inb = (seq >= 0 && seq < SEQ);
            float a0, a1;
            unpack2(acc[i], a0, a1);
            float y0 = fmaxf(a0 + bi0, 0.f);
            float y1 = fmaxf(a1 + bi1, 0.f);
            o0[u] = inb ? fmaf(y0, sc0, sh0) : 0.f;
            o1[u] = inb ? fmaf(y1, sc1, sh1) : 0.f;
        }
    }
}

__global__ void __launch_bounds__(NTHREADS, 1)
dna_fused_kernel(Ptrs P, float* __restrict__ out)
{
    extern __shared__ float sm[];
    const int tid = threadIdx.x;
    const int ts  = blockIdx.x * TSIZE;
    const int b   = blockIdx.y;
    const int seq_base = ts - HALO;

    float* bufA = sm + OFF_BUFA;
    float* bufB = sm + OFF_BUFB;
    float* sW[4] = { sm + OFF_W0, sm + OFF_W1, sm + OFF_W2, sm + OFF_W3 };
    float* sSC = sm + OFF_SC;
    float* sSH = sm + OFF_SH;
    float* sBI = sm + OFF_BI;
    float* sFW1 = sm + OFF_FW1;
    float* sFB1 = sm + OFF_FB1;
    float* sFW2 = sm + OFF_FW2;
    float* sFB2 = sm + OFF_FB2;

    // phase 1: halo-only zero fill of both activation buffers.
    {
        constexpr int ZPR = 8 + (WPAD - 512);   // 88 zeros per row
        for (int idx = tid; idx < 64 * ZPR; idx += NTHREADS) {
            int r = idx / ZPR, c = idx - r * ZPR;
            int u = (c < 8) ? c : (504 + c);
            sm[r * WPAD + u] = 0.f;
        }
    }

    const int cinK[4] = { 4 * 3, 32 * 3, 32 * 5, 32 * 7 };
#pragma unroll
    for (int l = 0; l < 4; ++l) {
        const int n = cinK[l];                 // per-channel weight count
        for (int i = tid; i < 16 * n; i += NTHREADS) {
            int cp = i / n, r = i - cp * n;
            sW[l][2 * i]     = P.w[l][(2 * cp)     * n + r];
            sW[l][2 * i + 1] = P.w[l][(2 * cp + 1) * n + r];
        }
    }

    for (int i = tid; i < 16 * 32; i += NTHREADS) sFW1[i] = P.fw1[i];
    if (tid < 16) { sFB1[tid] = P.fb1[tid]; sFW2[tid] = P.fw2[tid]; }
    if (tid == 0) sFB2[0] = P.fb2[0];

    if (tid < 128) {
        int l = tid >> 5, c = tid & 31;
        float inv = P.g[l][c] * rsqrtf(P.rv[l][c] + 1e-5f);
        sSC[tid] = inv;
        sSH[tid] = P.bb[l][c] - P.rm[l][c] * inv;
        sBI[tid] = P.b[l][c];
    }
    __syncthreads();

    // phase 2: input tile (4 channels, width 526) over the zeroed halo
    constexpr int WIN = TSIZE + 2 * HALO;   // 526
    for (int idx = tid; idx < 4 * WIN; idx += NTHREADS) {
        int cin = idx / WIN;
        int u = idx - cin * WIN;
        int seq = seq_base + u;
        if (seq >= 0 && seq < SEQ)
            bufA[cin * WPAD + u] = P.x[(b * 4 + cin) * SEQ + seq];
    }
    __syncthreads();

    const int cp = tid >> 5;    // warp -> channel pair [0,16)
    const int j  = tid & 31;    // lane -> position slice [0,32)

    conv_layer_cp<4, 3, 524, 1, 18, 4>(bufA, bufB, sW[0], sSC +  0, sSH +  0, sBI +  0, cp, j, seq_base);
    __syncthreads();
    conv_layer_cp<32, 3, 522, 2, 18, 1>(bufB, bufA, sW[1], sSC + 32, sSH + 32, sBI + 32, cp, j, seq_base);
    __syncthreads();
    conv_layer_cp<32, 5, 518, 4, 18, 1>(bufA, bufB, sW[2], sSC + 64, sSH + 64, sBI + 64, cp, j, seq_base);
    __syncthreads();
    conv_layer_cp<32, 7, 512, 7, 16, 1>(bufB, bufA, sW[3], sSC + 96, sSH + 96, sBI + 96, cp, j, seq_base);
    __syncthreads();

    // ---- per-position MLP: 32 -> 16 (ReLU) -> 1 ; one thread per position ----
    float yc[32];
#pragma unroll
    for (int c = 0; c < 32; ++c) yc[c] = bufA[c * WPAD + HALO + tid];

    float o = sFB2[0];
#pragma unroll
    for (int i = 0; i < 16; ++i) {
        float h = sFB1[i];
#pragma unroll
        for (int c = 0; c < 32; ++c) h = fmaf(sFW1[i * 32 + c], yc[c], h);
        o = fmaf(fmaxf(h, 0.f), sFW2[i], o);
    }
    out[b * SEQ + ts + tid] = o;
}

extern "C" void kernel_launch(void* const* d_in, const int* in_sizes, int n_in,
                              void* d_out, int out_size)
{
    Ptrs P;
    P.x = (const float*)d_in[0];
    for (int l = 0; l < 4; ++l) {
        P.w[l]  = (const float*)d_in[1 + 6 * l];
        P.b[l]  = (const float*)d_in[2 + 6 * l];
        P.g[l]  = (const float*)d_in[3 + 6 * l];
        P.bb[l] = (const float*)d_in[4 + 6 * l];
        P.rm[l] = (const float*)d_in[5 + 6 * l];
        P.rv[l] = (const float*)d_in[6 + 6 * l];
    }
    P.fw1 = (const float*)d_in[25];
    P.fb1 = (const float*)d_in[26];
    P.fw2 = (const float*)d_in[27];
    P.fb2 = (const float*)d_in[28];

    cudaFuncSetAttribute(dna_fused_kernel,
                         cudaFuncAttributeMaxDynamicSharedMemorySize, SMEM_BYTES);

    dim3 grid(SEQ / TSIZE, BATCH);
    dna_fused_kernel<<<grid, NTHREADS, SMEM_BYTES>>>(P, (float*)d_out);
}

// round 17
// speedup vs baseline: 1.3314x; 1.2678x over previous
#include <cuda_runtime.h>

// DNAShapeNet fused kernel, R14: R4 structure with TSIZE grown 512 -> 564
// (the 32x18-coverage limit). Tiles/batch 16 -> 15, waves 13.84 -> 12.97:
// -6.3% total FFMA2 at the measured rt-3 FMA-pipe wall. Chunk stays 18
// everywhere (odd-ish stride, conflict-free).

#define BATCH    128
#define SEQ      8192
#define TSIZE    564
#define TILES    15            // ceil(8192/564)
#define NTHREADS 512
#define WPAD     592
#define HALO     7

typedef unsigned long long ull;

// ---- smem layout (float offsets) ----
#define OFF_BUFA 0
#define OFF_BUFB (OFF_BUFA + 32*WPAD)
#define OFF_W0   (OFF_BUFB + 32*WPAD)
#define OFF_W1   (OFF_W0 + 384)
#define OFF_W2   (OFF_W1 + 3072)
#define OFF_W3   (OFF_W2 + 5120)
#define OFF_SC   (OFF_W3 + 7168)
#define OFF_SH   (OFF_SC + 128)
#define OFF_BI   (OFF_SH + 128)
#define OFF_FW1  (OFF_BI + 128)
#define OFF_FB1  (OFF_FW1 + 512)
#define OFF_FW2  (OFF_FB1 + 16)
#define OFF_FB2  (OFF_FW2 + 16)
#define SMEM_FLOATS (OFF_FB2 + 1)
#define SMEM_BYTES  (SMEM_FLOATS * 4)

struct Ptrs {
    const float* x;
    const float* w[4];
    const float* b[4];
    const float* g[4];
    const float* bb[4];
    const float* rm[4];
    const float* rv[4];
    const float* fw1;
    const float* fb1;
    const float* fw2;
    const float* fb2;
};

__device__ __forceinline__ ull pack2(float lo, float hi) {
    ull r;
    asm("mov.b64 %0, {%1, %2};" : "=l"(r) : "f"(lo), "f"(hi));
    return r;
}
__device__ __forceinline__ void unpack2(ull v, float& lo, float& hi) {
    asm("mov.b64 {%0, %1}, %2;" : "=f"(lo), "=f"(hi) : "l"(v));
}
__device__ __forceinline__ ull fma2(ull a, ull b, ull c) {
    ull d;
    asm("fma.rn.f32x2 %0, %1, %2, %3;" : "=l"(d) : "l"(a), "l"(b), "l"(c));
    return d;
}

// CH=18 output positions for one input channel, channel-pair packed.
template<int K, int SOFF>
__device__ __forceinline__ void conv_chunk_cp(const float* __restrict__ xin,
                                              const ull* __restrict__ wp,
                                              ull* __restrict__ acc)
{
    constexpr int NS = SOFF + 18 + K - 1;   // scalars spanned from even base
    constexpr int NP = (NS + 1) >> 1;       // float2 loads

    float s[2 * NP];
#pragma unroll
    for (int i = 0; i < NP; ++i) {
        float2 v = ((const float2*)xin)[i];
        s[2 * i] = v.x; s[2 * i + 1] = v.y;
    }

    ull bb[NS];                             // broadcast pairs {s,s}
#pragma unroll
    for (int u = SOFF; u < NS; ++u) bb[u] = pack2(s[u], s[u]);

#pragma unroll
    for (int t = 0; t < K; ++t)
#pragma unroll
        for (int p = 0; p < 18; ++p)
            acc[p] = fma2(bb[SOFF + p + t], wp[t], acc[p]);
}

// One conv+ReLU+BN layer, smem -> smem. Thread (cp, j) computes channels
// {2cp, 2cp+1} at 18 positions starting at LOFF + j*18.
template <int CIN, int K, int WOUT, int LOFF, int UNROLL>
__device__ __forceinline__ void conv_layer_cp(
    const float* __restrict__ sin, float* __restrict__ sout,
    const float* __restrict__ wint,
    const float* __restrict__ sc, const float* __restrict__ sh,
    const float* __restrict__ bi,
    int cp, int j, int seq_base)
{
    constexpr int H = K / 2;
    constexpr int DELTA = (LOFF - H) & 1;        // parity fix -> even base

    ull acc[18];
    const ull z = pack2(0.f, 0.f);
#pragma unroll
    for (int p = 0; p < 18; ++p) acc[p] = z;

    const int abase = (LOFF - H - DELTA) + j * 18;   // even

#pragma unroll UNROLL
    for (int cin = 0; cin < CIN; ++cin) {
        const ull* wsm = (const ull*)(wint + (cp * CIN + cin) * (2 * K));
        ull wp[K];
#pragma unroll
        for (int t = 0; t < K; ++t) wp[t] = wsm[t];   // LDS.64, warp-uniform

        conv_chunk_cp<K, DELTA>(sin + cin * WPAD + abase, wp, acc);
    }

    const int co0 = 2 * cp;
    const float sc0 = sc[co0], sh0 = sh[co0], bi0 = bi[co0];
    const float sc1 = sc[co0 + 1], sh1 = sh[co0 + 1], bi1 = bi[co0 + 1];
    float* o0 = sout + co0 * WPAD;
    float* o1 = o0 + WPAD;

#pragma unroll
    for (int i = 0; i < 18; ++i) {
        int pl = j * 18 + i;
        if (pl < WOUT) {
            int u = LOFF + pl;
            int seq = seq_base + u;
            bool inb = (seq >= 0 && seq < SEQ);
            float a0, a1;
            unpack2(acc[i], a0, a1);
            float y0 = fmaxf(a0 + bi0, 0.f);
            float y1 = fmaxf(a1 + bi1, 0.f);
            o0[u] = inb ? fmaf(y0, sc0, sh0) : 0.f;
            o1[u] = inb ? fmaf(y1, sc1, sh1) : 0.f;
        }
    }
}

__global__ void __launch_bounds__(NTHREADS, 1)
dna_fused_kernel(Ptrs P, float* __restrict__ out)
{
    extern __shared__ float sm[];
    const int tid = threadIdx.x;
    const int ts  = blockIdx.x * TSIZE;
    const int b   = blockIdx.y;
    const int seq_base = ts - HALO;

    float* bufA = sm + OFF_BUFA;
    float* bufB = sm + OFF_BUFB;
    float* sW[4] = { sm + OFF_W0, sm + OFF_W1, sm + OFF_W2, sm + OFF_W3 };
    float* sSC = sm + OFF_SC;
    float* sSH = sm + OFF_SH;
    float* sBI = sm + OFF_BI;
    float* sFW1 = sm + OFF_FW1;
    float* sFB1 = sm + OFF_FB1;
    float* sFW2 = sm + OFF_FW2;
    float* sFB2 = sm + OFF_FB2;

    // phase 1: halo-only zero fill of both activation buffers.
    // Per row: [0,8) and [TSIZE,WPAD) = [564,592) — all guard regions that
    // any layer reads but no earlier layer writes.
    {
        constexpr int ZPR = 8 + (WPAD - TSIZE);   // 36 zeros per row
        for (int idx = tid; idx < 64 * ZPR; idx += NTHREADS) {
            int r = idx / ZPR, c = idx - r * ZPR;
            int u = (c < 8) ? c : (TSIZE - 8 + c);
            sm[r * WPAD + u] = 0.f;
        }
    }

    const int cinK[4] = { 4 * 3, 32 * 3, 32 * 5, 32 * 7 };
#pragma unroll
    for (int l = 0; l < 4; ++l) {
        const int n = cinK[l];                 // per-channel weight count
        for (int i = tid; i < 16 * n; i += NTHREADS) {
            int cp = i / n, r = i - cp * n;
            sW[l][2 * i]     = P.w[l][(2 * cp)     * n + r];
            sW[l][2 * i + 1] = P.w[l][(2 * cp + 1) * n + r];
        }
    }

    for (int i = tid; i < 16 * 32; i += NTHREADS) sFW1[i] = P.fw1[i];
    if (tid < 16) { sFB1[tid] = P.fb1[tid]; sFW2[tid] = P.fw2[tid]; }
    if (tid == 0) sFB2[0] = P.fb2[0];

    if (tid < 128) {
        int l = tid >> 5, c = tid & 31;
        float inv = P.g[l][c] * rsqrtf(P.rv[l][c] + 1e-5f);
        sSC[tid] = inv;
        sSH[tid] = P.bb[l][c] - P.rm[l][c] * inv;
        sBI[tid] = P.b[l][c];
    }
    __syncthreads();

    // phase 2: input tile (4 channels, width 578) over the zeroed halo
    constexpr int WIN = TSIZE + 2 * HALO;   // 578
    for (int idx = tid; idx < 4 * WIN; idx += NTHREADS) {
        int cin = idx / WIN;
        int u = idx - cin * WIN;
        int seq = seq_base + u;
        bufA[cin * WPAD + u] =
            (seq >= 0 && seq < SEQ) ? P.x[(b * 4 + cin) * SEQ + seq] : 0.f;
    }
    __syncthreads();

    const int cp = tid >> 5;    // warp -> channel pair [0,16)
    const int j  = tid & 31;    // lane -> 18-pos slice [0,32)

    // widths: TSIZE+12 = 576 @ off 1 -> 574 @ 2 -> 570 @ 4 -> 564 @ 7
    conv_layer_cp<4, 3, TSIZE + 12, 1, 4>(bufA, bufB, sW[0], sSC +  0, sSH +  0, sBI +  0, cp, j, seq_base);
    __syncthreads();
    conv_layer_cp<32, 3, TSIZE + 10, 2, 1>(bufB, bufA, sW[1], sSC + 32, sSH + 32, sBI + 32, cp, j, seq_base);
    __syncthreads();
    conv_layer_cp<32, 5, TSIZE + 6, 4, 1>(bufA, bufB, sW[2], sSC + 64, sSH + 64, sBI + 64, cp, j, seq_base);
    __syncthreads();
    conv_layer_cp<32, 7, TSIZE, 7, 1>(bufB, bufA, sW[3], sSC + 96, sSH + 96, sBI + 96, cp, j, seq_base);
    __syncthreads();

    // ---- per-position MLP: 32 -> 16 (ReLU) -> 1 ----
    // 564 positions, 512 threads: threads 0..511 do pos=tid; 0..51 also tid+512.
#pragma unroll 1
    for (int pos = tid; pos < TSIZE; pos += NTHREADS) {
        int seq = ts + pos;
        if (seq >= SEQ) break;

        float yc[32];
#pragma unroll
        for (int c = 0; c < 32; ++c) yc[c] = bufA[c * WPAD + HALO + pos];

        float o = sFB2[0];
#pragma unroll
        for (int i = 0; i < 16; ++i) {
            float h = sFB1[i];
#pragma unroll
            for (int c = 0; c < 32; ++c) h = fmaf(sFW1[i * 32 + c], yc[c], h);
            o = fmaf(fmaxf(h, 0.f), sFW2[i], o);
        }
        out[b * SEQ + seq] = o;
    }
}

extern "C" void kernel_launch(void* const* d_in, const int* in_sizes, int n_in,
                              void* d_out, int out_size)
{
    Ptrs P;
    P.x = (const float*)d_in[0];
    for (int l = 0; l < 4; ++l) {
        P.w[l]  = (const float*)d_in[1 + 6 * l];
        P.b[l]  = (const float*)d_in[2 + 6 * l];
        P.g[l]  = (const float*)d_in[3 + 6 * l];
        P.bb[l] = (const float*)d_in[4 + 6 * l];
        P.rm[l] = (const float*)d_in[5 + 6 * l];
        P.rv[l] = (const float*)d_in[6 + 6 * l];
    }
    P.fw1 = (const float*)d_in[25];
    P.fb1 = (const float*)d_in[26];
    P.fw2 = (const float*)d_in[27];
    P.fb2 = (const float*)d_in[28];

    cudaFuncSetAttribute(dna_fused_kernel,
                         cudaFuncAttributeMaxDynamicSharedMemorySize, SMEM_BYTES);

    dim3 grid(TILES, BATCH);
    dna_fused_kernel<<<grid, NTHREADS, SMEM_BYTES>>>(P, (float*)d_out);
}